// round 3
// baseline (speedup 1.0000x reference)
#include <cuda_runtime.h>
#include <math.h>

#define N_ 4096
#define C_ 512
#define H_ 128
#define T_ 64
#define D_ 20
#define G3 384

// ------------------------- scratch (device globals) -------------------------
__device__ float g_gx[(size_t)T_ * N_ * G3];     // gx for layer0, reused for layer1
__device__ float g_out0[(size_t)T_ * N_ * H_];   // layer0 outputs (all steps)
__device__ float g_xh[N_ * H_];                  // x_hidden
__device__ float g_den[C_];
__device__ float g_s2c[(size_t)N_ * C_];
__device__ float g_hidC[C_ * H_];
__device__ float g_v1[C_];
__device__ float g_logits[(size_t)C_ * N_];      // logits^T, then s2c2^T after softmax
__device__ float g_hid2[C_ * H_];
__device__ float g_nx[N_];
__device__ float g_ny[C_];
__device__ float g_c2s[(size_t)N_ * C_];
__device__ float g_tmp[N_ * H_];
__device__ float g_ps[N_ * H_];
__device__ float g_hsh[N_ * H_];                 // h_shared
__device__ float g_outps[N_ * H_];
__device__ float g_nh[N_];
__device__ float g_diag[N_];
__device__ float g_big[(size_t)N_ * N_];         // hs2c then hc2s
__device__ float g_part[32 * N_];
__device__ float g_colsum[N_];
__device__ float g_hidH[N_ * H_];
__device__ float g_v2[N_];
__device__ float g_nhh[N_];
__device__ float g_hsi[N_ * H_];
__device__ float g_indi[N_ * H_];
__device__ float g_ouths[N_ * H_];
__device__ float g_outindi[N_ * H_];

__device__ __forceinline__ float sig_(float x) { return 1.f / (1.f + expf(-x)); }

// ------------------------- gx0: layer-0 input projection -------------------------
// gx[t][n][g] = b_ih0[g] + sum_d x[n][d*64 + t] * w_ih0[g][d]
__global__ void gx0_kernel(const float* __restrict__ x, const float* __restrict__ wih,
                           const float* __restrict__ bih, float* __restrict__ gx)
{
    __shared__ float xs[32 * D_];
    const int t = blockIdx.x;
    const int n0 = blockIdx.y * 32;
    const int g = threadIdx.x;  // 384 threads
    for (int idx = g; idx < 32 * D_; idx += G3) {
        int r = idx / D_, d = idx - r * D_;
        xs[idx] = x[(size_t)(n0 + r) * (D_ * T_) + d * T_ + t];
    }
    float wr[D_];
#pragma unroll
    for (int d = 0; d < D_; ++d) wr[d] = wih[g * D_ + d];
    const float b = bih[g];
    __syncthreads();
    for (int r = 0; r < 32; ++r) {
        const float4* xp = (const float4*)&xs[r * D_];
        float acc = b;
#pragma unroll
        for (int q = 0; q < 5; ++q) {
            float4 v = xp[q];
            acc += v.x * wr[q * 4 + 0] + v.y * wr[q * 4 + 1] +
                   v.z * wr[q * 4 + 2] + v.w * wr[q * 4 + 3];
        }
        gx[((size_t)t * N_ + n0 + r) * G3 + g] = acc;
    }
}

// ------------------------- persistent GRU layer -------------------------
// Block = 32 batch rows. smem: Whh^T [128][384], h [128][33], bhh [384].
// Warp wp owns gate-triples j in [16*wp, 16*wp+16); lane = batch row.
__global__ __launch_bounds__(256, 1) void gru_layer(
    const float* __restrict__ gx, const float* __restrict__ whh,
    const float* __restrict__ bhh, float* __restrict__ out, int write_all)
{
    extern __shared__ float sm[];
    float* W  = sm;                      // [k][g] : W[k*384+g] = whh[g*128+k]
    float* Hs = sm + 128 * G3;           // [j][r] stride 33
    float* Bb = Hs + 128 * 33;           // [384]
    const int tid = threadIdx.x, lane = tid & 31, wp = tid >> 5;
    const int n0 = blockIdx.x * 32;
    const int jb = wp * 16;

    for (int idx = tid; idx < G3 * 128; idx += 256) {
        int g = idx >> 7, k = idx & 127;
        W[k * G3 + g] = whh[idx];
    }
    for (int idx = tid; idx < 128 * 33; idx += 256) Hs[idx] = 0.f;
    for (int idx = tid; idx < G3; idx += 256) Bb[idx] = bhh[idx];
    __syncthreads();

    for (int t = 0; t < T_; ++t) {
        float aR[16], aZ[16], aN[16];
#pragma unroll
        for (int jj = 0; jj < 16; ++jj) {
            aR[jj] = Bb[jb + jj];
            aZ[jj] = Bb[128 + jb + jj];
            aN[jj] = Bb[256 + jb + jj];
        }
#pragma unroll 2
        for (int k = 0; k < 128; ++k) {
            const float hk = Hs[k * 33 + lane];
            const float4* wR = (const float4*)&W[k * G3 + jb];
            const float4* wZ = (const float4*)&W[k * G3 + 128 + jb];
            const float4* wN = (const float4*)&W[k * G3 + 256 + jb];
#pragma unroll
            for (int q = 0; q < 4; ++q) {
                float4 r4 = wR[q], z4 = wZ[q], n4 = wN[q];
                aR[q * 4 + 0] += hk * r4.x; aR[q * 4 + 1] += hk * r4.y;
                aR[q * 4 + 2] += hk * r4.z; aR[q * 4 + 3] += hk * r4.w;
                aZ[q * 4 + 0] += hk * z4.x; aZ[q * 4 + 1] += hk * z4.y;
                aZ[q * 4 + 2] += hk * z4.z; aZ[q * 4 + 3] += hk * z4.w;
                aN[q * 4 + 0] += hk * n4.x; aN[q * 4 + 1] += hk * n4.y;
                aN[q * 4 + 2] += hk * n4.z; aN[q * 4 + 3] += hk * n4.w;
            }
        }
        __syncthreads();
        // gate update (in-register), then write h back
        const float* gxp = gx + ((size_t)t * N_ + n0 + lane) * G3 + jb;
        float xr[16], xz[16], xn[16];
#pragma unroll
        for (int q = 0; q < 4; ++q) {
            float4 v = *(const float4*)(gxp + 4 * q);
            xr[4 * q] = v.x; xr[4 * q + 1] = v.y; xr[4 * q + 2] = v.z; xr[4 * q + 3] = v.w;
            v = *(const float4*)(gxp + 128 + 4 * q);
            xz[4 * q] = v.x; xz[4 * q + 1] = v.y; xz[4 * q + 2] = v.z; xz[4 * q + 3] = v.w;
            v = *(const float4*)(gxp + 256 + 4 * q);
            xn[4 * q] = v.x; xn[4 * q + 1] = v.y; xn[4 * q + 2] = v.z; xn[4 * q + 3] = v.w;
        }
#pragma unroll
        for (int jj = 0; jj < 16; ++jj) {
            float r = sig_(xr[jj] + aR[jj]);
            float z = sig_(xz[jj] + aZ[jj]);
            float nc = tanhf(xn[jj] + r * aN[jj]);
            float hold = Hs[(jb + jj) * 33 + lane];
            Hs[(jb + jj) * 33 + lane] = (1.f - z) * nc + z * hold;
        }
        __syncthreads();
        if (write_all) {
            float* op = out + ((size_t)t * N_ + n0) * H_;
            for (int idx = tid; idx < 32 * H_; idx += 256) {
                int r = idx >> 7, j = idx & 127;
                op[r * H_ + j] = Hs[j * 33 + r];
            }
        }
    }
    if (!write_all) {
        for (int idx = tid; idx < 32 * H_; idx += 256) {
            int r = idx >> 7, j = idx & 127;
            out[(size_t)(n0 + r) * H_ + j] = Hs[j * 33 + r];
        }
    }
}

// ------------------------- generic SGEMM 64x64x16 -------------------------
// TR: 0 = NN (A[M,K], B[K,N]) ; 1 = NT (A[M,K], B[N,K]) ; 2 = TN (A[K,M], B[K,N])
// EPI: 0 none ; 1 +bias[col] ; 2 +bias leaky ; 3 out = aux - (acc + bias)
template <int TR, int EPI>
__global__ void sgemm(const float* __restrict__ A, const float* __restrict__ B,
                      float* __restrict__ Cm, int M, int Nn, int K,
                      const float* __restrict__ bias, const float* __restrict__ aux)
{
    __shared__ float As[16][68];
    __shared__ float Bs[16][68];
    const int bm = blockIdx.y * 64, bn = blockIdx.x * 64;
    const int tid = threadIdx.x;
    const int tx = tid & 15, ty = tid >> 4;
    float acc[4][4] = {};
    for (int k0 = 0; k0 < K; k0 += 16) {
        if (TR == 2) {
            int k = tid >> 4, m = (tid & 15) << 2;
            float4 v = *(const float4*)&A[(size_t)(k0 + k) * M + bm + m];
            *(float4*)&As[k][m] = v;
        } else {
            int m = tid >> 2, k = (tid & 3) << 2;
            float4 v = *(const float4*)&A[(size_t)(bm + m) * K + k0 + k];
            As[k][m] = v.x; As[k + 1][m] = v.y; As[k + 2][m] = v.z; As[k + 3][m] = v.w;
        }
        if (TR == 1) {
            int n = tid >> 2, k = (tid & 3) << 2;
            float4 v = *(const float4*)&B[(size_t)(bn + n) * K + k0 + k];
            Bs[k][n] = v.x; Bs[k + 1][n] = v.y; Bs[k + 2][n] = v.z; Bs[k + 3][n] = v.w;
        } else {
            int k = tid >> 4, n = (tid & 15) << 2;
            float4 v = *(const float4*)&B[(size_t)(k0 + k) * Nn + bn + n];
            *(float4*)&Bs[k][n] = v;
        }
        __syncthreads();
#pragma unroll
        for (int kk = 0; kk < 16; ++kk) {
            float4 a = *(float4*)&As[kk][ty << 2];
            float4 b = *(float4*)&Bs[kk][tx << 2];
            acc[0][0] += a.x * b.x; acc[0][1] += a.x * b.y; acc[0][2] += a.x * b.z; acc[0][3] += a.x * b.w;
            acc[1][0] += a.y * b.x; acc[1][1] += a.y * b.y; acc[1][2] += a.y * b.z; acc[1][3] += a.y * b.w;
            acc[2][0] += a.z * b.x; acc[2][1] += a.z * b.y; acc[2][2] += a.z * b.z; acc[2][3] += a.z * b.w;
            acc[3][0] += a.w * b.x; acc[3][1] += a.w * b.y; acc[3][2] += a.w * b.z; acc[3][3] += a.w * b.w;
        }
        __syncthreads();
    }
#pragma unroll
    for (int i = 0; i < 4; ++i) {
        int row = bm + (ty << 2) + i;
#pragma unroll
        for (int j = 0; j < 4; ++j) {
            int col = bn + (tx << 2) + j;
            float v = acc[i][j];
            if (EPI >= 1) v += bias[col];
            if (EPI == 2) v = v > 0.f ? v : 0.01f * v;
            if (EPI == 3) v = aux[(size_t)row * Nn + col] - v;
            Cm[(size_t)row * Nn + col] = v;
        }
    }
}

// ------------------------- reductions / elementwise -------------------------
__global__ void colsum_part(const float* __restrict__ m, const float* __restrict__ w,
                            int rows, int cols, float* __restrict__ part)
{
    int c = blockIdx.x * 256 + threadIdx.x;
    int chunk = rows / gridDim.y;
    int r0 = blockIdx.y * chunk;
    float acc = 0.f;
    for (int r = r0; r < r0 + chunk; ++r)
        acc += m[(size_t)r * cols + c] * (w ? w[r] : 1.f);
    part[(size_t)blockIdx.y * cols + c] = acc;
}
__global__ void colsum_reduce(const float* __restrict__ part, int nb, int cols,
                              float* __restrict__ out)
{
    int c = blockIdx.x * 256 + threadIdx.x;
    float a = 0.f;
    for (int b = 0; b < nb; ++b) a += part[(size_t)b * cols + c];
    out[c] = a;
}

__global__ void s2c_kernel(const float* __restrict__ cm, const float* __restrict__ mv,
                           const float* __restrict__ den, float* __restrict__ s2c)
{
    int e = blockIdx.x * 256 + threadIdx.x;
    if (e >= N_ * C_) return;
    int i = e >> 9, c = e & (C_ - 1);
    float cv = cm[e];
    s2c[e] = cv * mv[i] / (den[c] * cv + 1.f);
}

// warp-per-row: norm / (sum!=0) flag / cos-diag
__global__ void rownorm(const float* __restrict__ x, int cols,
                        float* __restrict__ nrm, float* __restrict__ vflag,
                        float* __restrict__ dg)
{
    int row = blockIdx.x * 8 + (threadIdx.x >> 5);
    int lane = threadIdx.x & 31;
    const float* p = x + (size_t)row * cols;
    float s = 0.f, q = 0.f;
    for (int c = lane; c < cols; c += 32) { float v = p[c]; s += v; q += v * v; }
#pragma unroll
    for (int o = 16; o; o >>= 1) {
        s += __shfl_xor_sync(0xffffffffu, s, o);
        q += __shfl_xor_sync(0xffffffffu, q, o);
    }
    if (lane == 0) {
        if (nrm) nrm[row] = sqrtf(q);
        if (vflag) vflag[row] = (s != 0.f) ? 1.f : 0.f;
        if (dg) { float d = sqrtf(q) * sqrtf(q); dg[row] = q / fmaxf(d, 1e-12f); }
    }
}

// row softmax, optional cos-sim scaling (v / max(rs[row]*cs[col],1e-12)) and v-mask
__global__ void row_softmax(float* __restrict__ m, int width,
                            const float* __restrict__ rs, const float* __restrict__ cs,
                            const float* __restrict__ vm)
{
    extern __shared__ float sv[];
    __shared__ float red[8];
    __shared__ float smx, ssum;
    const int tid = threadIdx.x, lane = tid & 31, wid = tid >> 5;
    const size_t base = (size_t)blockIdx.x * width;
    const float rsv = rs ? rs[blockIdx.x] : 0.f;
    float lmax = -3.0e38f;
    for (int j = tid; j < width; j += 256) {
        float v = m[base + j];
        if (rs) v = v / fmaxf(rsv * cs[j], 1e-12f);
        if (vm && vm[j] == 0.f) v = -3.0e38f;
        sv[j] = v;
        lmax = fmaxf(lmax, v);
    }
#pragma unroll
    for (int o = 16; o; o >>= 1) lmax = fmaxf(lmax, __shfl_xor_sync(0xffffffffu, lmax, o));
    if (lane == 0) red[wid] = lmax;
    __syncthreads();
    if (tid == 0) {
        float v = red[0];
        for (int w = 1; w < 8; ++w) v = fmaxf(v, red[w]);
        smx = v;
    }
    __syncthreads();
    const float mx = smx;
    float lsum = 0.f;
    for (int j = tid; j < width; j += 256) {
        float e = expf(sv[j] - mx);
        sv[j] = e;
        lsum += e;
    }
#pragma unroll
    for (int o = 16; o; o >>= 1) lsum += __shfl_xor_sync(0xffffffffu, lsum, o);
    if (lane == 0) red[wid] = lsum;
    __syncthreads();
    if (tid == 0) {
        float v = 0.f;
        for (int w = 0; w < 8; ++w) v += red[w];
        ssum = v;
    }
    __syncthreads();
    const float inv = 1.f / ssum;
    for (int j = tid; j < width; j += 256) {
        float o = sv[j] * inv;
        if (vm) o = (vm[j] != 0.f) ? o : 0.f;
        m[base + j] = o;
    }
}

__global__ void scale_zerodiag(float* __restrict__ big, const float* __restrict__ nh)
{
    size_t e = (size_t)blockIdx.x * 256 + threadIdx.x;
    if (e >= (size_t)N_ * N_) return;
    int i = (int)(e >> 12), j = (int)(e & (N_ - 1));
    float v = big[e] / fmaxf(nh[i] * nh[j], 1e-12f);
    big[e] = (i == j) ? 0.f : v;
}

__global__ void topk_mask(float* __restrict__ m)
{
    __shared__ float vals[N_];
    __shared__ unsigned char flag[N_];
    __shared__ float rv[8];
    __shared__ int ri[8];
    const int tid = threadIdx.x, lane = tid & 31, wid = tid >> 5;
    const size_t base = (size_t)blockIdx.x * N_;
    for (int j = tid; j < N_; j += 256) { vals[j] = m[base + j]; flag[j] = 0; }
    __syncthreads();
    for (int s = 0; s < 10; ++s) {
        float bv = -3.0e38f; int bi = 0;
        for (int j = tid; j < N_; j += 256) {
            float v = vals[j];
            if (v > bv) { bv = v; bi = j; }
        }
#pragma unroll
        for (int o = 16; o; o >>= 1) {
            float ov = __shfl_down_sync(0xffffffffu, bv, o);
            int oi = __shfl_down_sync(0xffffffffu, bi, o);
            if (ov > bv || (ov == bv && oi < bi)) { bv = ov; bi = oi; }
        }
        if (lane == 0) { rv[wid] = bv; ri[wid] = bi; }
        __syncthreads();
        if (tid == 0) {
            float B = rv[0]; int I = ri[0];
            for (int w = 1; w < 8; ++w)
                if (rv[w] > B || (rv[w] == B && ri[w] < I)) { B = rv[w]; I = ri[w]; }
            flag[I] = 1;
            vals[I] = -3.0e38f;
        }
        __syncthreads();
    }
    for (int j = tid; j < N_; j += 256)
        if (!flag[j]) m[base + j] = 0.f;
}

__global__ void adddiag(float* __restrict__ big, const float* __restrict__ colsum,
                        const float* __restrict__ dg)
{
    int j = blockIdx.x * 256 + threadIdx.x;
    if (j < N_ && colsum[j] != 0.f)
        big[(size_t)j * N_ + j] += dg[j];
}

__global__ void final_head(const float* __restrict__ a, const float* __restrict__ b,
                           const float* __restrict__ c, const float* __restrict__ w,
                           const float* __restrict__ bo, float* __restrict__ out)
{
    int row = blockIdx.x * 8 + (threadIdx.x >> 5);
    int lane = threadIdx.x & 31;
    size_t base = (size_t)row * H_;
    float acc = 0.f;
    for (int h = lane; h < H_; h += 32)
        acc += (a[base + h] + b[base + h] + c[base + h]) * w[h];
#pragma unroll
    for (int o = 16; o; o >>= 1) acc += __shfl_xor_sync(0xffffffffu, acc, o);
    if (lane == 0) out[row] = acc + bo[0];
}

// ------------------------- host side -------------------------
static void sgemm_go(int TR, int EPI, const float* A, const float* B, float* Cm,
                     int M, int Nn, int K, const float* bias, const float* aux)
{
    dim3 g(Nn / 64, M / 64), blk(256);
    if (TR == 1 && EPI == 0) sgemm<1, 0><<<g, blk>>>(A, B, Cm, M, Nn, K, bias, aux);
    else if (TR == 1 && EPI == 1) sgemm<1, 1><<<g, blk>>>(A, B, Cm, M, Nn, K, bias, aux);
    else if (TR == 1 && EPI == 2) sgemm<1, 2><<<g, blk>>>(A, B, Cm, M, Nn, K, bias, aux);
    else if (TR == 1 && EPI == 3) sgemm<1, 3><<<g, blk>>>(A, B, Cm, M, Nn, K, bias, aux);
    else if (TR == 2) sgemm<2, 0><<<g, blk>>>(A, B, Cm, M, Nn, K, bias, aux);
    else sgemm<0, 0><<<g, blk>>>(A, B, Cm, M, Nn, K, bias, aux);
}

template <typename Tp>
static float* symaddr(Tp& sym)
{
    void* p = nullptr;
    cudaGetSymbolAddress(&p, sym);
    return (float*)p;
}

extern "C" void kernel_launch(void* const* d_in, const int* in_sizes, int n_in,
                              void* d_out, int out_size)
{
    const float* x = (const float*)d_in[0];
    const float* cm = (const float*)d_in[1];
    const float* mv = (const float*)d_in[2];
    const float* wih0 = (const float*)d_in[3];
    const float* whh0 = (const float*)d_in[4];
    const float* bih0 = (const float*)d_in[5];
    const float* bhh0 = (const float*)d_in[6];
    const float* wih1 = (const float*)d_in[7];
    const float* whh1 = (const float*)d_in[8];
    const float* bih1 = (const float*)d_in[9];
    const float* bhh1 = (const float*)d_in[10];
    const float* w_ps = (const float*)d_in[11];
    const float* b_ps = (const float*)d_in[12];
    const float* w_hs = (const float*)d_in[13];
    const float* b_hs = (const float*)d_in[14];
    const float* w_ps_fore = (const float*)d_in[15];
    const float* b_ps_fore = (const float*)d_in[16];
    const float* w_hs_fore = (const float*)d_in[17];
    const float* b_hs_fore = (const float*)d_in[18];
    const float* w_ps_back = (const float*)d_in[19];
    const float* b_ps_back = (const float*)d_in[20];
    const float* w_hs_back = (const float*)d_in[21];
    const float* b_hs_back = (const float*)d_in[22];
    const float* w_indi = (const float*)d_in[23];
    const float* b_indi = (const float*)d_in[24];
    const float* w_out = (const float*)d_in[25];
    const float* b_out = (const float*)d_in[26];
    float* out = (float*)d_out;

    float* gx = symaddr(g_gx);
    float* out0 = symaddr(g_out0);
    float* xh = symaddr(g_xh);
    float* den = symaddr(g_den);
    float* s2c = symaddr(g_s2c);
    float* hidC = symaddr(g_hidC);
    float* v1 = symaddr(g_v1);
    float* logits = symaddr(g_logits);
    float* hid2 = symaddr(g_hid2);
    float* nx = symaddr(g_nx);
    float* ny = symaddr(g_ny);
    float* c2s = symaddr(g_c2s);
    float* tmp = symaddr(g_tmp);
    float* ps = symaddr(g_ps);
    float* hsh = symaddr(g_hsh);
    float* outps = symaddr(g_outps);
    float* nh = symaddr(g_nh);
    float* dg = symaddr(g_diag);
    float* big = symaddr(g_big);
    float* part = symaddr(g_part);
    float* colsum = symaddr(g_colsum);
    float* hidH = symaddr(g_hidH);
    float* v2 = symaddr(g_v2);
    float* nhh = symaddr(g_nhh);
    float* hsi = symaddr(g_hsi);
    float* indi = symaddr(g_indi);
    float* ouths = symaddr(g_ouths);
    float* outindi = symaddr(g_outindi);

    const int GRU_SMEM = (128 * G3 + 128 * 33 + G3) * 4;
    cudaFuncSetAttribute(gru_layer, cudaFuncAttributeMaxDynamicSharedMemorySize, GRU_SMEM);

    // ---- GRU ----
    gx0_kernel<<<dim3(T_, N_ / 32), G3>>>(x, wih0, bih0, gx);
    gru_layer<<<N_ / 32, 256, GRU_SMEM>>>(gx, whh0, bhh0, out0, 1);
    sgemm_go(1, 1, out0, wih1, gx, T_ * N_, G3, H_, bih1, nullptr);   // gx1 = out0 @ wih1^T + b
    gru_layer<<<N_ / 32, 256, GRU_SMEM>>>(gx, whh1, bhh1, xh, 0);

    // ---- predefined-concept branch ----
    colsum_part<<<dim3(C_ / 256, 32), 256>>>(cm, mv, N_, C_, part);
    colsum_reduce<<<C_ / 256, 256>>>(part, 32, C_, den);
    s2c_kernel<<<(N_ * C_) / 256, 256>>>(cm, mv, den, s2c);
    sgemm_go(2, 0, s2c, xh, hidC, C_, H_, N_, nullptr, nullptr);      // hidden = s2c^T @ xh
    rownorm<<<C_ / 8, 256>>>(hidC, H_, nullptr, v1, nullptr);
    sgemm_go(1, 0, hidC, xh, logits, C_, N_, H_, nullptr, nullptr);   // logits^T [C,N]
    row_softmax<<<C_, 256, N_ * 4>>>(logits, N_, nullptr, nullptr, nullptr); // col-softmax
    sgemm_go(0, 0, logits, xh, hid2, C_, H_, N_, nullptr, nullptr);   // hidden2
    rownorm<<<N_ / 8, 256>>>(xh, H_, nx, nullptr, nullptr);
    rownorm<<<C_ / 8, 256>>>(hid2, H_, ny, nullptr, nullptr);
    sgemm_go(1, 0, xh, hid2, c2s, N_, C_, H_, nullptr, nullptr);      // cos numerator
    row_softmax<<<N_, 256, C_ * 4>>>(c2s, C_, nx, ny, v1);            // scale+mask+softmax*v1
    sgemm_go(0, 0, c2s, hid2, tmp, N_, H_, C_, nullptr, nullptr);     // p_shared0
    sgemm_go(1, 1, tmp, w_ps, ps, N_, H_, H_, b_ps, nullptr);         // p_shared
    sgemm_go(1, 3, ps, w_ps_back, hsh, N_, H_, H_, b_ps_back, xh);    // h_shared = xh - p_back
    sgemm_go(1, 2, ps, w_ps_fore, outps, N_, H_, H_, b_ps_fore, nullptr); // out_ps

    // ---- hidden-concept branch ----
    rownorm<<<N_ / 8, 256>>>(hsh, H_, nh, nullptr, dg);
    sgemm_go(1, 0, hsh, hsh, big, N_, N_, H_, nullptr, nullptr);      // hs2c numerator
    scale_zerodiag<<<(int)(((size_t)N_ * N_) / 256), 256>>>(big, nh);
    topk_mask<<<N_, 256>>>(big);
    colsum_part<<<dim3(N_ / 256, 32), 256>>>(big, nullptr, N_, N_, part);
    colsum_reduce<<<N_ / 256, 256>>>(part, 32, N_, colsum);
    adddiag<<<N_ / 256, 256>>>(big, colsum, dg);
    sgemm_go(2, 0, big, hsh, hidH, N_, H_, N_, nullptr, nullptr);     // hidden_h = masked^T @ hsh
    rownorm<<<N_ / 8, 256>>>(hidH, H_, nhh, v2, nullptr);
    sgemm_go(1, 0, hsh, hidH, big, N_, N_, H_, nullptr, nullptr);     // hc2s numerator
    row_softmax<<<N_, 256, N_ * 4>>>(big, N_, nh, nhh, v2);
    sgemm_go(0, 0, big, hidH, tmp, N_, H_, N_, nullptr, nullptr);     // h_si0
    sgemm_go(1, 1, tmp, w_hs, hsi, N_, H_, H_, b_hs, nullptr);        // h_si
    sgemm_go(1, 3, hsi, w_hs_back, indi, N_, H_, H_, b_hs_back, hsh); // indi = hsh - h_back
    sgemm_go(1, 2, hsi, w_hs_fore, ouths, N_, H_, H_, b_hs_fore, nullptr); // out_hs
    sgemm_go(1, 2, indi, w_indi, outindi, N_, H_, H_, b_indi, nullptr);    // out_indi

    // ---- head ----
    final_head<<<N_ / 8, 256>>>(outps, ouths, outindi, w_out, b_out, out);
}

// round 4
// speedup vs baseline: 1.3026x; 1.3026x over previous
#include <cuda_runtime.h>
#include <math.h>

#define N_ 4096
#define C_ 512
#define H_ 128
#define T_ 64
#define D_ 20
#define G3 384

typedef unsigned long long u64;

// ------------------------- f32x2 helpers -------------------------
__device__ __forceinline__ u64 pack2_(float x) {
    u64 r; asm("mov.b64 %0, {%1, %2};" : "=l"(r) : "f"(x), "f"(x)); return r;
}
__device__ __forceinline__ u64 pack2ab_(float a, float b) {
    u64 r; asm("mov.b64 %0, {%1, %2};" : "=l"(r) : "f"(a), "f"(b)); return r;
}
__device__ __forceinline__ void fma2_(u64& d, u64 a, u64 b) {
    asm("fma.rn.f32x2 %0, %1, %2, %0;" : "+l"(d) : "l"(a), "l"(b));
}
__device__ __forceinline__ void unpack2_(u64 v, float& lo, float& hi) {
    asm("mov.b64 {%0, %1}, %2;" : "=f"(lo), "=f"(hi) : "l"(v));
}

// ------------------------- scratch (device globals) -------------------------
__device__ float g_gx[(size_t)T_ * N_ * G3];
__device__ float g_out0[(size_t)T_ * N_ * H_];
__device__ float g_xh[N_ * H_];
__device__ float g_den[C_];
__device__ float g_s2c[(size_t)N_ * C_];
__device__ float g_hidC[C_ * H_];
__device__ float g_v1[C_];
__device__ float g_logits[(size_t)C_ * N_];
__device__ float g_hid2[C_ * H_];
__device__ float g_nx[N_];
__device__ float g_ny[C_];
__device__ float g_c2s[(size_t)N_ * C_];
__device__ float g_tmp[N_ * H_];
__device__ float g_ps[N_ * H_];
__device__ float g_hsh[N_ * H_];
__device__ float g_outps[N_ * H_];
__device__ float g_nh[N_];
__device__ float g_diag[N_];
__device__ float g_big[(size_t)N_ * N_];
__device__ float g_part[32 * N_];
__device__ float g_kpart[(size_t)16 * N_ * H_];   // split-K partials (max 16 x 4096 x 128)
__device__ float g_colsum[N_];
__device__ float g_hidH[N_ * H_];
__device__ float g_v2[N_];
__device__ float g_nhh[N_];
__device__ float g_hsi[N_ * H_];
__device__ float g_indi[N_ * H_];
__device__ float g_ouths[N_ * H_];
__device__ float g_outindi[N_ * H_];

__device__ __forceinline__ float sig_(float x) { return 1.f / (1.f + __expf(-x)); }

// ------------------------- gx0: layer-0 input projection -------------------------
__global__ void gx0_kernel(const float* __restrict__ x, const float* __restrict__ wih,
                           const float* __restrict__ bih, float* __restrict__ gx)
{
    __shared__ float xs[32 * D_];
    const int t = blockIdx.x;
    const int n0 = blockIdx.y * 32;
    const int g = threadIdx.x;  // 384 threads
    for (int idx = g; idx < 32 * D_; idx += G3) {
        int r = idx / D_, d = idx - r * D_;
        xs[idx] = x[(size_t)(n0 + r) * (D_ * T_) + d * T_ + t];
    }
    float wr[D_];
#pragma unroll
    for (int d = 0; d < D_; ++d) wr[d] = wih[g * D_ + d];
    const float b = bih[g];
    __syncthreads();
    for (int r = 0; r < 32; ++r) {
        const float4* xp = (const float4*)&xs[r * D_];
        float acc = b;
#pragma unroll
        for (int q = 0; q < 5; ++q) {
            float4 v = xp[q];
            acc += v.x * wr[q * 4 + 0] + v.y * wr[q * 4 + 1] +
                   v.z * wr[q * 4 + 2] + v.w * wr[q * 4 + 3];
        }
        gx[((size_t)t * N_ + n0 + r) * G3 + g] = acc;
    }
}

// ------------------------- persistent GRU layer (f32x2) -------------------------
// Block = 32 batch rows, 512 threads (16 warps). Warp wp owns hidden units
// j in [8*wp, 8*wp+8). lane = batch row. Whh^T resident in smem.
__global__ __launch_bounds__(512, 1) void gru_layer(
    const float* __restrict__ gx, const float* __restrict__ whh,
    const float* __restrict__ bhh, float* __restrict__ out, int write_all)
{
    extern __shared__ float sm[];
    float* W  = sm;                      // [k][g] : W[k*384+g] = whh[g*128+k]
    float* Hs = sm + 128 * G3;           // [j][r] stride 33
    float* Bb = Hs + 128 * 33;           // [384]
    const int tid = threadIdx.x, lane = tid & 31, wp = tid >> 5;
    const int n0 = blockIdx.x * 32;
    const int jb = wp * 8;

    for (int idx = tid; idx < G3 * 128; idx += 512) {
        int g = idx >> 7, k = idx & 127;
        W[k * G3 + g] = whh[idx];
    }
    for (int idx = tid; idx < 128 * 33; idx += 512) Hs[idx] = 0.f;
    for (int idx = tid; idx < G3; idx += 512) Bb[idx] = bhh[idx];
    __syncthreads();

    for (int t = 0; t < T_; ++t) {
        // prefetch gx for this step (latency hides under the k-loop)
        const float* gxp = gx + ((size_t)t * N_ + n0 + lane) * G3 + jb;
        float4 xr0 = *(const float4*)(gxp);
        float4 xr1 = *(const float4*)(gxp + 4);
        float4 xz0 = *(const float4*)(gxp + 128);
        float4 xz1 = *(const float4*)(gxp + 132);
        float4 xn0 = *(const float4*)(gxp + 256);
        float4 xn1 = *(const float4*)(gxp + 260);

        u64 aR[4] = {0, 0, 0, 0}, aZ[4] = {0, 0, 0, 0}, aN[4] = {0, 0, 0, 0};
#pragma unroll 4
        for (int k = 0; k < 128; ++k) {
            const float hk = Hs[k * 33 + lane];
            const u64 h2 = pack2_(hk);
            const float* wb = &W[k * G3 + jb];
            ulonglong2 r01 = *(const ulonglong2*)(wb);
            ulonglong2 r23 = *(const ulonglong2*)(wb + 4);
            ulonglong2 z01 = *(const ulonglong2*)(wb + 128);
            ulonglong2 z23 = *(const ulonglong2*)(wb + 132);
            ulonglong2 n01 = *(const ulonglong2*)(wb + 256);
            ulonglong2 n23 = *(const ulonglong2*)(wb + 260);
            fma2_(aR[0], h2, r01.x); fma2_(aR[1], h2, r01.y);
            fma2_(aR[2], h2, r23.x); fma2_(aR[3], h2, r23.y);
            fma2_(aZ[0], h2, z01.x); fma2_(aZ[1], h2, z01.y);
            fma2_(aZ[2], h2, z23.x); fma2_(aZ[3], h2, z23.y);
            fma2_(aN[0], h2, n01.x); fma2_(aN[1], h2, n01.y);
            fma2_(aN[2], h2, n23.x); fma2_(aN[3], h2, n23.y);
        }
        __syncthreads();

        float gr[8], gz[8], gn[8];
#pragma unroll
        for (int p = 0; p < 4; ++p) {
            unpack2_(aR[p], gr[2 * p], gr[2 * p + 1]);
            unpack2_(aZ[p], gz[2 * p], gz[2 * p + 1]);
            unpack2_(aN[p], gn[2 * p], gn[2 * p + 1]);
        }
        float xr[8] = {xr0.x, xr0.y, xr0.z, xr0.w, xr1.x, xr1.y, xr1.z, xr1.w};
        float xz[8] = {xz0.x, xz0.y, xz0.z, xz0.w, xz1.x, xz1.y, xz1.z, xz1.w};
        float xn[8] = {xn0.x, xn0.y, xn0.z, xn0.w, xn1.x, xn1.y, xn1.z, xn1.w};
#pragma unroll
        for (int jj = 0; jj < 8; ++jj) {
            float r = sig_(xr[jj] + gr[jj] + Bb[jb + jj]);
            float z = sig_(xz[jj] + gz[jj] + Bb[128 + jb + jj]);
            float nc = tanhf(xn[jj] + r * (gn[jj] + Bb[256 + jb + jj]));
            float hold = Hs[(jb + jj) * 33 + lane];
            Hs[(jb + jj) * 33 + lane] = (1.f - z) * nc + z * hold;
        }
        __syncthreads();
        if (write_all) {
            float* op = out + ((size_t)t * N_ + n0) * H_;
            for (int idx = tid; idx < 32 * H_; idx += 512) {
                int r = idx >> 7, j = idx & 127;
                op[r * H_ + j] = Hs[j * 33 + r];
            }
        }
    }
    if (!write_all) {
        for (int idx = tid; idx < 32 * H_; idx += 512) {
            int r = idx >> 7, j = idx & 127;
            out[(size_t)(n0 + r) * H_ + j] = Hs[j * 33 + r];
        }
    }
}

// ------------------------- 128x128 f32x2 SGEMM with split-K -------------------------
// TR: 0 = NN (A[M,K], B[K,N]) ; 1 = NT (A[M,K], B[N,K]) ; 2 = TN (A[K,M], B[K,N])
// EPI: 0 none ; 1 +bias[col] ; 2 +bias, leaky ; 3 aux - (acc + bias) ;
//      4 cos-scale acc/max(nr[row]*nc[col],1e-12), zero diag
template <int EPI>
__device__ __forceinline__ float epi_apply(float v, int row, int col, int Nn,
                                           const float* e1, const float* e2)
{
    if (EPI == 1) v += e1[col];
    if (EPI == 2) { v += e1[col]; v = v > 0.f ? v : 0.01f * v; }
    if (EPI == 3) { v += e1[col]; v = e2[(size_t)row * Nn + col] - v; }
    if (EPI == 4) {
        v = v / fmaxf(e1[row] * e2[col], 1e-12f);
        if (row == col) v = 0.f;
    }
    return v;
}

template <int TR, int EPI>
__global__ __launch_bounds__(256, 2) void sgemm128(
    const float* __restrict__ A, const float* __restrict__ B, float* __restrict__ Cm,
    int M, int Nn, int K, int Ksplit,
    const float* __restrict__ e1, const float* __restrict__ e2,
    float* __restrict__ part)
{
    __shared__ __align__(16) float As[16][136];
    __shared__ __align__(16) float Bs[16][136];
    const int bm = blockIdx.y * 128, bn = blockIdx.x * 128;
    const int z = blockIdx.z;
    const int kb = z * Ksplit, ke = kb + Ksplit;
    const int tid = threadIdx.x;
    const int tx = tid & 15, ty = tid >> 4;
    u64 acc[4][8];
#pragma unroll
    for (int i = 0; i < 4; ++i)
#pragma unroll
        for (int j = 0; j < 8; ++j) acc[i][j] = 0ull;

    for (int k0 = kb; k0 < ke; k0 += 16) {
        if (TR == 2) {            // A[K,M]
            int k = tid >> 4, m = (tid & 15) << 3;
            const float* src = &A[(size_t)(k0 + k) * M + bm + m];
            *(float4*)&As[k][m]     = *(const float4*)(src);
            *(float4*)&As[k][m + 4] = *(const float4*)(src + 4);
        } else {                  // A[M,K]
            int m = tid >> 1, kq = (tid & 1) << 3;
            const float* src = &A[(size_t)(bm + m) * K + k0 + kq];
            float4 v0 = *(const float4*)(src);
            float4 v1 = *(const float4*)(src + 4);
            As[kq + 0][m] = v0.x; As[kq + 1][m] = v0.y;
            As[kq + 2][m] = v0.z; As[kq + 3][m] = v0.w;
            As[kq + 4][m] = v1.x; As[kq + 5][m] = v1.y;
            As[kq + 6][m] = v1.z; As[kq + 7][m] = v1.w;
        }
        if (TR == 1) {            // B[N,K]
            int n = tid >> 1, kq = (tid & 1) << 3;
            const float* src = &B[(size_t)(bn + n) * K + k0 + kq];
            float4 v0 = *(const float4*)(src);
            float4 v1 = *(const float4*)(src + 4);
            Bs[kq + 0][n] = v0.x; Bs[kq + 1][n] = v0.y;
            Bs[kq + 2][n] = v0.z; Bs[kq + 3][n] = v0.w;
            Bs[kq + 4][n] = v1.x; Bs[kq + 5][n] = v1.y;
            Bs[kq + 6][n] = v1.z; Bs[kq + 7][n] = v1.w;
        } else {                  // B[K,N]
            int k = tid >> 4, n = (tid & 15) << 3;
            const float* src = &B[(size_t)(k0 + k) * Nn + bn + n];
            *(float4*)&Bs[k][n]     = *(const float4*)(src);
            *(float4*)&Bs[k][n + 4] = *(const float4*)(src + 4);
        }
        __syncthreads();
#pragma unroll
        for (int kk = 0; kk < 16; ++kk) {
            ulonglong2 a01 = *(const ulonglong2*)&As[kk][ty << 3];
            ulonglong2 a23 = *(const ulonglong2*)&As[kk][(ty << 3) + 4];
            float4 b0 = *(const float4*)&Bs[kk][tx << 2];
            float4 b1 = *(const float4*)&Bs[kk][64 + (tx << 2)];
            u64 ar[4] = {a01.x, a01.y, a23.x, a23.y};
            u64 bd[8];
            bd[0] = pack2_(b0.x); bd[1] = pack2_(b0.y);
            bd[2] = pack2_(b0.z); bd[3] = pack2_(b0.w);
            bd[4] = pack2_(b1.x); bd[5] = pack2_(b1.y);
            bd[6] = pack2_(b1.z); bd[7] = pack2_(b1.w);
#pragma unroll
            for (int rp = 0; rp < 4; ++rp)
#pragma unroll
                for (int c = 0; c < 8; ++c) fma2_(acc[rp][c], ar[rp], bd[c]);
        }
        __syncthreads();
    }

    const bool partial = (gridDim.z > 1);
    float* obase = partial ? part + (size_t)z * M * Nn : Cm;
#pragma unroll
    for (int rp = 0; rp < 4; ++rp) {
        float lo[8], hi[8];
#pragma unroll
        for (int c = 0; c < 8; ++c) unpack2_(acc[rp][c], lo[c], hi[c]);
        int row0 = bm + (ty << 3) + rp * 2;
#pragma unroll
        for (int h = 0; h < 2; ++h) {
            int row = row0 + h;
            float* vv = h ? hi : lo;
            int colA = bn + (tx << 2);
            int colB = bn + 64 + (tx << 2);
            float4 oA, oB;
            if (!partial) {
                oA.x = epi_apply<EPI>(vv[0], row, colA + 0, Nn, e1, e2);
                oA.y = epi_apply<EPI>(vv[1], row, colA + 1, Nn, e1, e2);
                oA.z = epi_apply<EPI>(vv[2], row, colA + 2, Nn, e1, e2);
                oA.w = epi_apply<EPI>(vv[3], row, colA + 3, Nn, e1, e2);
                oB.x = epi_apply<EPI>(vv[4], row, colB + 0, Nn, e1, e2);
                oB.y = epi_apply<EPI>(vv[5], row, colB + 1, Nn, e1, e2);
                oB.z = epi_apply<EPI>(vv[6], row, colB + 2, Nn, e1, e2);
                oB.w = epi_apply<EPI>(vv[7], row, colB + 3, Nn, e1, e2);
            } else {
                oA = make_float4(vv[0], vv[1], vv[2], vv[3]);
                oB = make_float4(vv[4], vv[5], vv[6], vv[7]);
            }
            *(float4*)&obase[(size_t)row * Nn + colA] = oA;
            *(float4*)&obase[(size_t)row * Nn + colB] = oB;
        }
    }
}

// split-K reduce (plain sum; all split-K calls use EPI=0)
__global__ void kreduce(const float* __restrict__ part, int S, size_t MN,
                        float* __restrict__ out)
{
    size_t i4 = ((size_t)blockIdx.x * 256 + threadIdx.x) * 4;
    if (i4 >= MN) return;
    float4 s = *(const float4*)&part[i4];
    for (int z = 1; z < S; ++z) {
        float4 v = *(const float4*)&part[(size_t)z * MN + i4];
        s.x += v.x; s.y += v.y; s.z += v.z; s.w += v.w;
    }
    *(float4*)&out[i4] = s;
}

// ------------------------- reductions / elementwise -------------------------
__global__ void colsum_part(const float* __restrict__ m, const float* __restrict__ w,
                            int rows, int cols, float* __restrict__ part)
{
    int c = blockIdx.x * 256 + threadIdx.x;
    int chunk = rows / gridDim.y;
    int r0 = blockIdx.y * chunk;
    float acc = 0.f;
    for (int r = r0; r < r0 + chunk; ++r)
        acc += m[(size_t)r * cols + c] * (w ? w[r] : 1.f);
    part[(size_t)blockIdx.y * cols + c] = acc;
}
__global__ void colsum_reduce(const float* __restrict__ part, int nb, int cols,
                              float* __restrict__ out)
{
    int c = blockIdx.x * 256 + threadIdx.x;
    float a = 0.f;
    for (int b = 0; b < nb; ++b) a += part[(size_t)b * cols + c];
    out[c] = a;
}

__global__ void s2c_kernel(const float* __restrict__ cm, const float* __restrict__ mv,
                           const float* __restrict__ den, float* __restrict__ s2c)
{
    int e = blockIdx.x * 256 + threadIdx.x;
    if (e >= N_ * C_) return;
    int i = e >> 9, c = e & (C_ - 1);
    float cv = cm[e];
    s2c[e] = cv * mv[i] / (den[c] * cv + 1.f);
}

__global__ void rownorm(const float* __restrict__ x, int cols,
                        float* __restrict__ nrm, float* __restrict__ vflag,
                        float* __restrict__ dg)
{
    int row = blockIdx.x * 8 + (threadIdx.x >> 5);
    int lane = threadIdx.x & 31;
    const float* p = x + (size_t)row * cols;
    float s = 0.f, q = 0.f;
    for (int c = lane; c < cols; c += 32) { float v = p[c]; s += v; q += v * v; }
#pragma unroll
    for (int o = 16; o; o >>= 1) {
        s += __shfl_xor_sync(0xffffffffu, s, o);
        q += __shfl_xor_sync(0xffffffffu, q, o);
    }
    if (lane == 0) {
        if (nrm) nrm[row] = sqrtf(q);
        if (vflag) vflag[row] = (s != 0.f) ? 1.f : 0.f;
        if (dg) { float d = sqrtf(q) * sqrtf(q); dg[row] = q / fmaxf(d, 1e-12f); }
    }
}

__global__ void row_softmax(float* __restrict__ m, int width,
                            const float* __restrict__ rs, const float* __restrict__ cs,
                            const float* __restrict__ vm)
{
    extern __shared__ float sv[];
    __shared__ float red[8];
    __shared__ float smx, ssum;
    const int tid = threadIdx.x, lane = tid & 31, wid = tid >> 5;
    const size_t base = (size_t)blockIdx.x * width;
    const float rsv = rs ? rs[blockIdx.x] : 0.f;
    float lmax = -3.0e38f;
    for (int j = tid; j < width; j += 256) {
        float v = m[base + j];
        if (rs) v = v / fmaxf(rsv * cs[j], 1e-12f);
        if (vm && vm[j] == 0.f) v = -3.0e38f;
        sv[j] = v;
        lmax = fmaxf(lmax, v);
    }
#pragma unroll
    for (int o = 16; o; o >>= 1) lmax = fmaxf(lmax, __shfl_xor_sync(0xffffffffu, lmax, o));
    if (lane == 0) red[wid] = lmax;
    __syncthreads();
    if (tid == 0) {
        float v = red[0];
        for (int w = 1; w < 8; ++w) v = fmaxf(v, red[w]);
        smx = v;
    }
    __syncthreads();
    const float mx = smx;
    float lsum = 0.f;
    for (int j = tid; j < width; j += 256) {
        float e = expf(sv[j] - mx);
        sv[j] = e;
        lsum += e;
    }
#pragma unroll
    for (int o = 16; o; o >>= 1) lsum += __shfl_xor_sync(0xffffffffu, lsum, o);
    if (lane == 0) red[wid] = lsum;
    __syncthreads();
    if (tid == 0) {
        float v = 0.f;
        for (int w = 0; w < 8; ++w) v += red[w];
        ssum = v;
    }
    __syncthreads();
    const float inv = 1.f / ssum;
    for (int j = tid; j < width; j += 256) {
        float o = sv[j] * inv;
        if (vm) o = (vm[j] != 0.f) ? o : 0.f;
        m[base + j] = o;
    }
}

__global__ void topk_mask(float* __restrict__ m)
{
    __shared__ float vals[N_];
    __shared__ unsigned char flag[N_];
    __shared__ float rv[8];
    __shared__ int ri[8];
    const int tid = threadIdx.x, lane = tid & 31, wid = tid >> 5;
    const size_t base = (size_t)blockIdx.x * N_;
    for (int j = tid; j < N_; j += 256) { vals[j] = m[base + j]; flag[j] = 0; }
    __syncthreads();
    for (int s = 0; s < 10; ++s) {
        float bv = -3.0e38f; int bi = 0;
        for (int j = tid; j < N_; j += 256) {
            float v = vals[j];
            if (v > bv) { bv = v; bi = j; }
        }
#pragma unroll
        for (int o = 16; o; o >>= 1) {
            float ov = __shfl_down_sync(0xffffffffu, bv, o);
            int oi = __shfl_down_sync(0xffffffffu, bi, o);
            if (ov > bv || (ov == bv && oi < bi)) { bv = ov; bi = oi; }
        }
        if (lane == 0) { rv[wid] = bv; ri[wid] = bi; }
        __syncthreads();
        if (tid == 0) {
            float B = rv[0]; int I = ri[0];
            for (int w = 1; w < 8; ++w)
                if (rv[w] > B || (rv[w] == B && ri[w] < I)) { B = rv[w]; I = ri[w]; }
            flag[I] = 1;
            vals[I] = -3.0e38f;
        }
        __syncthreads();
    }
    for (int j = tid; j < N_; j += 256)
        if (!flag[j]) m[base + j] = 0.f;
}

__global__ void adddiag(float* __restrict__ big, const float* __restrict__ colsum,
                        const float* __restrict__ dg)
{
    int j = blockIdx.x * 256 + threadIdx.x;
    if (j < N_ && colsum[j] != 0.f)
        big[(size_t)j * N_ + j] += dg[j];
}

__global__ void final_head(const float* __restrict__ a, const float* __restrict__ b,
                           const float* __restrict__ c, const float* __restrict__ w,
                           const float* __restrict__ bo, float* __restrict__ out)
{
    int row = blockIdx.x * 8 + (threadIdx.x >> 5);
    int lane = threadIdx.x & 31;
    size_t base = (size_t)row * H_;
    float acc = 0.f;
    for (int h = lane; h < H_; h += 32)
        acc += (a[base + h] + b[base + h] + c[base + h]) * w[h];
#pragma unroll
    for (int o = 16; o; o >>= 1) acc += __shfl_xor_sync(0xffffffffu, acc, o);
    if (lane == 0) out[row] = acc + bo[0];
}

// ------------------------- host side -------------------------
static float* g_kpart_ptr;

static void gemm(int TR, int EPI, const float* A, const float* B, float* Cm,
                 int M, int Nn, int K, int S, const float* e1, const float* e2)
{
    dim3 g(Nn / 128, M / 128, S), blk(256);
    int Ks = K / S;
    if (S > 1) {
        // partials (no epilogue), then reduce; all split-K users have EPI=0
        if (TR == 0) sgemm128<0, 0><<<g, blk>>>(A, B, Cm, M, Nn, K, Ks, e1, e2, g_kpart_ptr);
        else if (TR == 1) sgemm128<1, 0><<<g, blk>>>(A, B, Cm, M, Nn, K, Ks, e1, e2, g_kpart_ptr);
        else sgemm128<2, 0><<<g, blk>>>(A, B, Cm, M, Nn, K, Ks, e1, e2, g_kpart_ptr);
        size_t MN = (size_t)M * Nn;
        kreduce<<<(int)((MN / 4 + 255) / 256), 256>>>(g_kpart_ptr, S, MN, Cm);
        return;
    }
    if (TR == 0) sgemm128<0, 0><<<g, blk>>>(A, B, Cm, M, Nn, K, Ks, e1, e2, nullptr);
    else if (TR == 2) sgemm128<2, 0><<<g, blk>>>(A, B, Cm, M, Nn, K, Ks, e1, e2, nullptr);
    else if (EPI == 0) sgemm128<1, 0><<<g, blk>>>(A, B, Cm, M, Nn, K, Ks, e1, e2, nullptr);
    else if (EPI == 1) sgemm128<1, 1><<<g, blk>>>(A, B, Cm, M, Nn, K, Ks, e1, e2, nullptr);
    else if (EPI == 2) sgemm128<1, 2><<<g, blk>>>(A, B, Cm, M, Nn, K, Ks, e1, e2, nullptr);
    else if (EPI == 3) sgemm128<1, 3><<<g, blk>>>(A, B, Cm, M, Nn, K, Ks, e1, e2, nullptr);
    else sgemm128<1, 4><<<g, blk>>>(A, B, Cm, M, Nn, K, Ks, e1, e2, nullptr);
}

template <typename Tp>
static float* symaddr(Tp& sym)
{
    void* p = nullptr;
    cudaGetSymbolAddress(&p, sym);
    return (float*)p;
}

extern "C" void kernel_launch(void* const* d_in, const int* in_sizes, int n_in,
                              void* d_out, int out_size)
{
    const float* x = (const float*)d_in[0];
    const float* cm = (const float*)d_in[1];
    const float* mv = (const float*)d_in[2];
    const float* wih0 = (const float*)d_in[3];
    const float* whh0 = (const float*)d_in[4];
    const float* bih0 = (const float*)d_in[5];
    const float* bhh0 = (const float*)d_in[6];
    const float* wih1 = (const float*)d_in[7];
    const float* whh1 = (const float*)d_in[8];
    const float* bih1 = (const float*)d_in[9];
    const float* bhh1 = (const float*)d_in[10];
    const float* w_ps = (const float*)d_in[11];
    const float* b_ps = (const float*)d_in[12];
    const float* w_hs = (const float*)d_in[13];
    const float* b_hs = (const float*)d_in[14];
    const float* w_ps_fore = (const float*)d_in[15];
    const float* b_ps_fore = (const float*)d_in[16];
    const float* w_hs_fore = (const float*)d_in[17];
    const float* b_hs_fore = (const float*)d_in[18];
    const float* w_ps_back = (const float*)d_in[19];
    const float* b_ps_back = (const float*)d_in[20];
    const float* w_hs_back = (const float*)d_in[21];
    const float* b_hs_back = (const float*)d_in[22];
    const float* w_indi = (const float*)d_in[23];
    const float* b_indi = (const float*)d_in[24];
    const float* w_out = (const float*)d_in[25];
    const float* b_out = (const float*)d_in[26];
    float* out = (float*)d_out;

    float* gx = symaddr(g_gx);
    float* out0 = symaddr(g_out0);
    float* xh = symaddr(g_xh);
    float* den = symaddr(g_den);
    float* s2c = symaddr(g_s2c);
    float* hidC = symaddr(g_hidC);
    float* v1 = symaddr(g_v1);
    float* logits = symaddr(g_logits);
    float* hid2 = symaddr(g_hid2);
    float* nx = symaddr(g_nx);
    float* ny = symaddr(g_ny);
    float* c2s = symaddr(g_c2s);
    float* tmp = symaddr(g_tmp);
    float* ps = symaddr(g_ps);
    float* hsh = symaddr(g_hsh);
    float* outps = symaddr(g_outps);
    float* nh = symaddr(g_nh);
    float* dg = symaddr(g_diag);
    float* big = symaddr(g_big);
    float* part = symaddr(g_part);
    float* colsum = symaddr(g_colsum);
    float* hidH = symaddr(g_hidH);
    float* v2 = symaddr(g_v2);
    float* nhh = symaddr(g_nhh);
    float* hsi = symaddr(g_hsi);
    float* indi = symaddr(g_indi);
    float* ouths = symaddr(g_ouths);
    float* outindi = symaddr(g_outindi);
    g_kpart_ptr = symaddr(g_kpart);

    const int GRU_SMEM = (128 * G3 + 128 * 33 + G3) * 4;
    cudaFuncSetAttribute(gru_layer, cudaFuncAttributeMaxDynamicSharedMemorySize, GRU_SMEM);

    // ---- GRU ----
    gx0_kernel<<<dim3(T_, N_ / 32), G3>>>(x, wih0, bih0, gx);
    gru_layer<<<N_ / 32, 512, GRU_SMEM>>>(gx, whh0, bhh0, out0, 1);
    gemm(1, 1, out0, wih1, gx, T_ * N_, G3, H_, 1, bih1, nullptr);     // gx1
    gru_layer<<<N_ / 32, 512, GRU_SMEM>>>(gx, whh1, bhh1, xh, 0);

    // ---- predefined-concept branch ----
    colsum_part<<<dim3(C_ / 256, 32), 256>>>(cm, mv, N_, C_, part);
    colsum_reduce<<<C_ / 256, 256>>>(part, 32, C_, den);
    s2c_kernel<<<(N_ * C_) / 256, 256>>>(cm, mv, den, s2c);
    gemm(2, 0, s2c, xh, hidC, C_, H_, N_, 16, nullptr, nullptr);       // hidden = s2c^T @ xh
    rownorm<<<C_ / 8, 256>>>(hidC, H_, nullptr, v1, nullptr);
    gemm(1, 0, hidC, xh, logits, C_, N_, H_, 1, nullptr, nullptr);     // logits^T [C,N]
    row_softmax<<<C_, 256, N_ * 4>>>(logits, N_, nullptr, nullptr, nullptr);
    gemm(0, 0, logits, xh, hid2, C_, H_, N_, 16, nullptr, nullptr);    // hidden2
    rownorm<<<N_ / 8, 256>>>(xh, H_, nx, nullptr, nullptr);
    rownorm<<<C_ / 8, 256>>>(hid2, H_, ny, nullptr, nullptr);
    gemm(1, 0, xh, hid2, c2s, N_, C_, H_, 1, nullptr, nullptr);        // cos numerator
    row_softmax<<<N_, 256, C_ * 4>>>(c2s, C_, nx, ny, v1);
    gemm(0, 0, c2s, hid2, tmp, N_, H_, C_, 4, nullptr, nullptr);       // p_shared0
    gemm(1, 1, tmp, w_ps, ps, N_, H_, H_, 1, b_ps, nullptr);           // p_shared
    gemm(1, 3, ps, w_ps_back, hsh, N_, H_, H_, 1, b_ps_back, xh);      // h_shared
    gemm(1, 2, ps, w_ps_fore, outps, N_, H_, H_, 1, b_ps_fore, nullptr);

    // ---- hidden-concept branch ----
    rownorm<<<N_ / 8, 256>>>(hsh, H_, nh, nullptr, dg);
    gemm(1, 4, hsh, hsh, big, N_, N_, H_, 1, nh, nh);                  // hs2c fused scale+zerodiag
    topk_mask<<<N_, 256>>>(big);
    colsum_part<<<dim3(N_ / 256, 32), 256>>>(big, nullptr, N_, N_, part);
    colsum_reduce<<<N_ / 256, 256>>>(part, 32, N_, colsum);
    adddiag<<<N_ / 256, 256>>>(big, colsum, dg);
    gemm(2, 0, big, hsh, hidH, N_, H_, N_, 16, nullptr, nullptr);      // hidden_h
    rownorm<<<N_ / 8, 256>>>(hidH, H_, nhh, v2, nullptr);
    gemm(1, 0, hsh, hidH, big, N_, N_, H_, 1, nullptr, nullptr);       // hc2s numerator
    row_softmax<<<N_, 256, N_ * 4>>>(big, N_, nh, nhh, v2);
    gemm(0, 0, big, hidH, tmp, N_, H_, N_, 16, nullptr, nullptr);      // h_si0
    gemm(1, 1, tmp, w_hs, hsi, N_, H_, H_, 1, b_hs, nullptr);          // h_si
    gemm(1, 3, hsi, w_hs_back, indi, N_, H_, H_, 1, b_hs_back, hsh);   // indi
    gemm(1, 2, hsi, w_hs_fore, ouths, N_, H_, H_, 1, b_hs_fore, nullptr);
    gemm(1, 2, indi, w_indi, outindi, N_, H_, H_, 1, b_indi, nullptr);

    // ---- head ----
    final_head<<<N_ / 8, 256>>>(outps, ouths, outindi, w_out, b_out, out);
}

// round 6
// speedup vs baseline: 1.3303x; 1.0213x over previous
#include <cuda_runtime.h>
#include <cuda_bf16.h>
#include <math.h>
#include <stdint.h>

#define N_ 4096
#define C_ 512
#define H_ 128
#define T_ 64
#define D_ 20
#define G3 384

typedef unsigned long long u64;

// ------------------------- f32x2 helpers -------------------------
__device__ __forceinline__ u64 pack2_(float x) {
    u64 r; asm("mov.b64 %0, {%1, %2};" : "=l"(r) : "f"(x), "f"(x)); return r;
}
__device__ __forceinline__ void fma2_(u64& d, u64 a, u64 b) {
    asm("fma.rn.f32x2 %0, %1, %2, %0;" : "+l"(d) : "l"(a), "l"(b));
}
__device__ __forceinline__ void unpack2_(u64 v, float& lo, float& hi) {
    asm("mov.b64 {%0, %1}, %2;" : "=f"(lo), "=f"(hi) : "l"(v));
}

// fast activations (ex2.approx + rcp.approx; rel err ~1e-6)
__device__ __forceinline__ float fsig_(float x) {
    float e, r;
    asm("ex2.approx.f32 %0, %1;" : "=f"(e) : "f"(-1.4426950408889634f * x));
    asm("rcp.approx.f32 %0, %1;" : "=f"(r) : "f"(1.f + e));
    return r;
}
__device__ __forceinline__ float ftanh_(float x) {
    float e, r;
    asm("ex2.approx.f32 %0, %1;" : "=f"(e) : "f"(2.8853900817779268f * x));
    asm("rcp.approx.f32 %0, %1;" : "=f"(r) : "f"(1.f + e));
    return fmaf(-2.f, r, 1.f);
}

// ------------------------- mma.sync helpers (sm_80+, no arch suffix) -------------------------
__device__ __forceinline__ uint32_t smem_u32_(const void* p) {
    uint32_t a;
    asm("{ .reg .u64 t; cvta.to.shared.u64 t, %1; cvt.u32.u64 %0, t; }" : "=r"(a) : "l"(p));
    return a;
}
__device__ __forceinline__ void ldsm4_(uint32_t* r, uint32_t a) {
    asm volatile("ldmatrix.sync.aligned.m8n8.x4.shared.b16 {%0,%1,%2,%3}, [%4];"
                 : "=r"(r[0]), "=r"(r[1]), "=r"(r[2]), "=r"(r[3]) : "r"(a));
}
__device__ __forceinline__ void ldsm2_(uint32_t* r, uint32_t a) {
    asm volatile("ldmatrix.sync.aligned.m8n8.x2.shared.b16 {%0,%1}, [%2];"
                 : "=r"(r[0]), "=r"(r[1]) : "r"(a));
}
__device__ __forceinline__ void mma_bf16_(float* d, const uint32_t* a, const uint32_t* b) {
    asm volatile(
        "mma.sync.aligned.m16n8k16.row.col.f32.bf16.bf16.f32 "
        "{%0,%1,%2,%3}, {%4,%5,%6,%7}, {%8,%9}, {%0,%1,%2,%3};"
        : "+f"(d[0]), "+f"(d[1]), "+f"(d[2]), "+f"(d[3])
        : "r"(a[0]), "r"(a[1]), "r"(a[2]), "r"(a[3]), "r"(b[0]), "r"(b[1]));
}

// ------------------------- scratch (device globals) -------------------------
__device__ float g_gx[(size_t)T_ * N_ * G3];
__device__ float g_out0[(size_t)T_ * N_ * H_];
__device__ float g_xh[N_ * H_];
__device__ float g_den[C_];
__device__ float g_s2c[(size_t)N_ * C_];
__device__ float g_hidC[C_ * H_];
__device__ float g_v1[C_];
__device__ float g_logits[(size_t)C_ * N_];
__device__ float g_hid2[C_ * H_];
__device__ float g_nx[N_];
__device__ float g_ny[C_];
__device__ float g_c2s[(size_t)N_ * C_];
__device__ float g_tmp[N_ * H_];
__device__ float g_ps[N_ * H_];
__device__ float g_hsh[N_ * H_];
__device__ float g_outps[N_ * H_];
__device__ float g_nh[N_];
__device__ float g_diag[N_];
__device__ float g_big[(size_t)N_ * N_];
__device__ float g_part[32 * N_];
__device__ float g_kpart[(size_t)16 * N_ * H_];
__device__ float g_colsum[N_];
__device__ float g_hidH[N_ * H_];
__device__ float g_v2[N_];
__device__ float g_nhh[N_];
__device__ float g_hsi[N_ * H_];
__device__ float g_indi[N_ * H_];
__device__ float g_ouths[N_ * H_];
__device__ float g_outindi[N_ * H_];

// ==================== mma.sync bf16-split NT GEMM (K=128) ====================
// C[M,N] = A[M,128] * B[N,128]^T, fp32 via split bf16 (3 passes: hi*hi, lo*hi, hi*lo)
#define MM_PAD 136
#define MM_TILE_BYTES (128 * MM_PAD * 2)   // 34816
#define MM_SMEM (4 * MM_TILE_BYTES)        // 139264

__device__ __forceinline__ void cvt_split_(float4 v, uint2& hw, uint2& lw) {
    __nv_bfloat16 h0 = __float2bfloat16(v.x), h1 = __float2bfloat16(v.y);
    __nv_bfloat16 h2 = __float2bfloat16(v.z), h3 = __float2bfloat16(v.w);
    __nv_bfloat162 hp0 = __halves2bfloat162(h0, h1);
    __nv_bfloat162 hp1 = __halves2bfloat162(h2, h3);
    __nv_bfloat162 lp0 = __halves2bfloat162(
        __float2bfloat16(v.x - __bfloat162float(h0)),
        __float2bfloat16(v.y - __bfloat162float(h1)));
    __nv_bfloat162 lp1 = __halves2bfloat162(
        __float2bfloat16(v.z - __bfloat162float(h2)),
        __float2bfloat16(v.w - __bfloat162float(h3)));
    hw.x = *(uint32_t*)&hp0; hw.y = *(uint32_t*)&hp1;
    lw.x = *(uint32_t*)&lp0; lw.y = *(uint32_t*)&lp1;
}

// EPI: 0 plain ; 1 +bias[col] ; 4 cos-scale /max(e1[row]*e2[col],1e-12) + zero diag
template <int EPI>
__device__ __forceinline__ float mepi_(float v, int row, int col,
                                       const float* e1, const float* e2)
{
    if (EPI == 1) v += e1[col];
    if (EPI == 4) {
        v = v / fmaxf(e1[row] * e2[col], 1e-12f);
        if (row == col) v = 0.f;
    }
    return v;
}

template <int EPI>
__global__ __launch_bounds__(256, 1) void mmagemm(
    const float* __restrict__ A, const float* __restrict__ B, float* __restrict__ Cm,
    int M, int Nn, const float* __restrict__ e1, const float* __restrict__ e2)
{
    extern __shared__ __align__(16) char msm[];
    __nv_bfloat16* Ah = (__nv_bfloat16*)msm;
    __nv_bfloat16* Al = (__nv_bfloat16*)(msm + MM_TILE_BYTES);
    __nv_bfloat16* Bh = (__nv_bfloat16*)(msm + 2 * MM_TILE_BYTES);
    __nv_bfloat16* Bl = (__nv_bfloat16*)(msm + 3 * MM_TILE_BYTES);
    const int tid = threadIdx.x, lane = tid & 31, wid = tid >> 5;
    const int bm = blockIdx.y * 128, bn = blockIdx.x * 128;

    // load fp32 tiles, convert to hi/lo bf16
    {
        const float* Ab = A + (size_t)bm * 128;
        const float* Bb = B + (size_t)bn * 128;
        for (int idx = tid; idx < 128 * 32; idx += 256) {
            int row = idx >> 5, q = (idx & 31) << 2;
            uint2 hw, lw;
            cvt_split_(*(const float4*)&Ab[row * 128 + q], hw, lw);
            *(uint2*)&Ah[row * MM_PAD + q] = hw;
            *(uint2*)&Al[row * MM_PAD + q] = lw;
            cvt_split_(*(const float4*)&Bb[row * 128 + q], hw, lw);
            *(uint2*)&Bh[row * MM_PAD + q] = hw;
            *(uint2*)&Bl[row * MM_PAD + q] = lw;
        }
    }
    __syncthreads();

    const uint32_t sb = smem_u32_(msm);
    const int m0 = (wid >> 2) * 64, n0 = (wid & 3) * 32;
    const uint32_t aRow = (uint32_t)((m0 + (lane & 15)) * MM_PAD * 2 + (lane >> 4) * 16);
    const uint32_t bRow = (uint32_t)((n0 + (lane & 7)) * MM_PAD * 2 + ((lane >> 3) & 1) * 16);

    float acc[4][4][4];
#pragma unroll
    for (int i = 0; i < 4; ++i)
#pragma unroll
        for (int j = 0; j < 4; ++j)
#pragma unroll
            for (int q = 0; q < 4; ++q) acc[i][j][q] = 0.f;

#pragma unroll
    for (int p = 0; p < 3; ++p) {
        const uint32_t aB = sb + (p == 1 ? MM_TILE_BYTES : 0) + aRow;
        const uint32_t bB = sb + 2 * MM_TILE_BYTES + (p == 2 ? MM_TILE_BYTES : 0) + bRow;
#pragma unroll
        for (int k0 = 0; k0 < 128; k0 += 16) {
            uint32_t af[4][4], bf[4][2];
#pragma unroll
            for (int i = 0; i < 4; ++i) ldsm4_(af[i], aB + i * 16 * MM_PAD * 2 + k0 * 2);
#pragma unroll
            for (int j = 0; j < 4; ++j) ldsm2_(bf[j], bB + j * 8 * MM_PAD * 2 + k0 * 2);
#pragma unroll
            for (int i = 0; i < 4; ++i)
#pragma unroll
                for (int j = 0; j < 4; ++j) mma_bf16_(acc[i][j], af[i], bf[j]);
        }
    }

    const int tr = lane >> 2, tc = (lane & 3) * 2;
#pragma unroll
    for (int i = 0; i < 4; ++i) {
#pragma unroll
        for (int j = 0; j < 4; ++j) {
            int row = bm + m0 + i * 16 + tr;
            int col = bn + n0 + j * 8 + tc;
            float2 v0, v1;
            v0.x = mepi_<EPI>(acc[i][j][0], row, col, e1, e2);
            v0.y = mepi_<EPI>(acc[i][j][1], row, col + 1, e1, e2);
            v1.x = mepi_<EPI>(acc[i][j][2], row + 8, col, e1, e2);
            v1.y = mepi_<EPI>(acc[i][j][3], row + 8, col + 1, e1, e2);
            *(float2*)&Cm[(size_t)row * Nn + col] = v0;
            *(float2*)&Cm[(size_t)(row + 8) * Nn + col] = v1;
        }
    }
}

// ------------------------- gx0: layer-0 input projection -------------------------
__global__ void gx0_kernel(const float* __restrict__ x, const float* __restrict__ wih,
                           const float* __restrict__ bih, float* __restrict__ gx)
{
    __shared__ float xs[32 * D_];
    const int t = blockIdx.x;
    const int n0 = blockIdx.y * 32;
    const int g = threadIdx.x;  // 384 threads
    for (int idx = g; idx < 32 * D_; idx += G3) {
        int r = idx / D_, d = idx - r * D_;
        xs[idx] = x[(size_t)(n0 + r) * (D_ * T_) + d * T_ + t];
    }
    float wr[D_];
#pragma unroll
    for (int d = 0; d < D_; ++d) wr[d] = wih[g * D_ + d];
    const float b = bih[g];
    __syncthreads();
    for (int r = 0; r < 32; ++r) {
        const float4* xp = (const float4*)&xs[r * D_];
        float acc = b;
#pragma unroll
        for (int q = 0; q < 5; ++q) {
            float4 v = xp[q];
            acc += v.x * wr[q * 4 + 0] + v.y * wr[q * 4 + 1] +
                   v.z * wr[q * 4 + 2] + v.w * wr[q * 4 + 3];
        }
        gx[((size_t)t * N_ + n0 + r) * G3 + g] = acc;
    }
}

// ------------------------- persistent GRU layer (f32x2) -------------------------
__global__ __launch_bounds__(512, 1) void gru_layer(
    const float* __restrict__ gx, const float* __restrict__ whh,
    const float* __restrict__ bhh, float* __restrict__ out, int write_all)
{
    extern __shared__ float sm[];
    float* W  = sm;                      // [k][g]
    float* Hs = sm + 128 * G3;           // [j][r] stride 33
    float* Bb = Hs + 128 * 33;           // [384]
    const int tid = threadIdx.x, lane = tid & 31, wp = tid >> 5;
    const int n0 = blockIdx.x * 32;
    const int jb = wp * 8;

    for (int idx = tid; idx < G3 * 128; idx += 512) {
        int g = idx >> 7, k = idx & 127;
        W[k * G3 + g] = whh[idx];
    }
    for (int idx = tid; idx < 128 * 33; idx += 512) Hs[idx] = 0.f;
    for (int idx = tid; idx < G3; idx += 512) Bb[idx] = bhh[idx];
    __syncthreads();

    for (int t = 0; t < T_; ++t) {
        const float* gxp = gx + ((size_t)t * N_ + n0 + lane) * G3 + jb;
        float4 xr0 = *(const float4*)(gxp);
        float4 xr1 = *(const float4*)(gxp + 4);
        float4 xz0 = *(const float4*)(gxp + 128);
        float4 xz1 = *(const float4*)(gxp + 132);
        float4 xn0 = *(const float4*)(gxp + 256);
        float4 xn1 = *(const float4*)(gxp + 260);

        u64 aR[4] = {0, 0, 0, 0}, aZ[4] = {0, 0, 0, 0}, aN[4] = {0, 0, 0, 0};
#pragma unroll 4
        for (int k = 0; k < 128; ++k) {
            const float hk = Hs[k * 33 + lane];
            const u64 h2 = pack2_(hk);
            const float* wb = &W[k * G3 + jb];
            ulonglong2 r01 = *(const ulonglong2*)(wb);
            ulonglong2 r23 = *(const ulonglong2*)(wb + 4);
            ulonglong2 z01 = *(const ulonglong2*)(wb + 128);
            ulonglong2 z23 = *(const ulonglong2*)(wb + 132);
            ulonglong2 n01 = *(const ulonglong2*)(wb + 256);
            ulonglong2 n23 = *(const ulonglong2*)(wb + 260);
            fma2_(aR[0], h2, r01.x); fma2_(aR[1], h2, r01.y);
            fma2_(aR[2], h2, r23.x); fma2_(aR[3], h2, r23.y);
            fma2_(aZ[0], h2, z01.x); fma2_(aZ[1], h2, z01.y);
            fma2_(aZ[2], h2, z23.x); fma2_(aZ[3], h2, z23.y);
            fma2_(aN[0], h2, n01.x); fma2_(aN[1], h2, n01.y);
            fma2_(aN[2], h2, n23.x); fma2_(aN[3], h2, n23.y);
        }
        __syncthreads();

        float gr[8], gz[8], gn[8];
#pragma unroll
        for (int p = 0; p < 4; ++p) {
            unpack2_(aR[p], gr[2 * p], gr[2 * p + 1]);
            unpack2_(aZ[p], gz[2 * p], gz[2 * p + 1]);
            unpack2_(aN[p], gn[2 * p], gn[2 * p + 1]);
        }
        float xr[8] = {xr0.x, xr0.y, xr0.z, xr0.w, xr1.x, xr1.y, xr1.z, xr1.w};
        float xz[8] = {xz0.x, xz0.y, xz0.z, xz0.w, xz1.x, xz1.y, xz1.z, xz1.w};
        float xn[8] = {xn0.x, xn0.y, xn0.z, xn0.w, xn1.x, xn1.y, xn1.z, xn1.w};
#pragma unroll
        for (int jj = 0; jj < 8; ++jj) {
            float r = fsig_(xr[jj] + gr[jj] + Bb[jb + jj]);
            float z = fsig_(xz[jj] + gz[jj] + Bb[128 + jb + jj]);
            float nc = ftanh_(xn[jj] + r * (gn[jj] + Bb[256 + jb + jj]));
            float hold = Hs[(jb + jj) * 33 + lane];
            Hs[(jb + jj) * 33 + lane] = (1.f - z) * nc + z * hold;
        }
        __syncthreads();
        if (write_all) {
            float* op = out + ((size_t)t * N_ + n0) * H_;
            for (int idx = tid; idx < 32 * H_; idx += 512) {
                int r = idx >> 7, j = idx & 127;
                op[r * H_ + j] = Hs[j * 33 + r];
            }
        }
    }
    if (!write_all) {
        for (int idx = tid; idx < 32 * H_; idx += 512) {
            int r = idx >> 7, j = idx & 127;
            out[(size_t)(n0 + r) * H_ + j] = Hs[j * 33 + r];
        }
    }
}

// ------------------------- 128x128 f32x2 SGEMM with split-K -------------------------
template <int EPI>
__device__ __forceinline__ float epi_apply(float v, int row, int col, int Nn,
                                           const float* e1, const float* e2)
{
    if (EPI == 1) v += e1[col];
    if (EPI == 2) { v += e1[col]; v = v > 0.f ? v : 0.01f * v; }
    if (EPI == 3) { v += e1[col]; v = e2[(size_t)row * Nn + col] - v; }
    return v;
}

template <int TR, int EPI>
__global__ __launch_bounds__(256, 2) void sgemm128(
    const float* __restrict__ A, const float* __restrict__ B, float* __restrict__ Cm,
    int M, int Nn, int K, int Ksplit,
    const float* __restrict__ e1, const float* __restrict__ e2,
    float* __restrict__ part)
{
    __shared__ __align__(16) float As[16][136];
    __shared__ __align__(16) float Bs[16][136];
    const int bm = blockIdx.y * 128, bn = blockIdx.x * 128;
    const int z = blockIdx.z;
    const int kb = z * Ksplit, ke = kb + Ksplit;
    const int tid = threadIdx.x;
    const int tx = tid & 15, ty = tid >> 4;
    u64 acc[4][8];
#pragma unroll
    for (int i = 0; i < 4; ++i)
#pragma unroll
        for (int j = 0; j < 8; ++j) acc[i][j] = 0ull;

    for (int k0 = kb; k0 < ke; k0 += 16) {
        if (TR == 2) {
            int k = tid >> 4, m = (tid & 15) << 3;
            const float* src = &A[(size_t)(k0 + k) * M + bm + m];
            *(float4*)&As[k][m]     = *(const float4*)(src);
            *(float4*)&As[k][m + 4] = *(const float4*)(src + 4);
        } else {
            int m = tid >> 1, kq = (tid & 1) << 3;
            const float* src = &A[(size_t)(bm + m) * K + k0 + kq];
            float4 v0 = *(const float4*)(src);
            float4 v1 = *(const float4*)(src + 4);
            As[kq + 0][m] = v0.x; As[kq + 1][m] = v0.y;
            As[kq + 2][m] = v0.z; As[kq + 3][m] = v0.w;
            As[kq + 4][m] = v1.x; As[kq + 5][m] = v1.y;
            As[kq + 6][m] = v1.z; As[kq + 7][m] = v1.w;
        }
        if (TR == 1) {
            int n = tid >> 1, kq = (tid & 1) << 3;
            const float* src = &B[(size_t)(bn + n) * K + k0 + kq];
            float4 v0 = *(const float4*)(src);
            float4 v1 = *(const float4*)(src + 4);
            Bs[kq + 0][n] = v0.x; Bs[kq + 1][n] = v0.y;
            Bs[kq + 2][n] = v0.z; Bs[kq + 3][n] = v0.w;
            Bs[kq + 4][n] = v1.x; Bs[kq + 5][n] = v1.y;
            Bs[kq + 6][n] = v1.z; Bs[kq + 7][n] = v1.w;
        } else {
            int k = tid >> 4, n = (tid & 15) << 3;
            const float* src = &B[(size_t)(k0 + k) * Nn + bn + n];
            *(float4*)&Bs[k][n]     = *(const float4*)(src);
            *(float4*)&Bs[k][n + 4] = *(const float4*)(src + 4);
        }
        __syncthreads();
#pragma unroll
        for (int kk = 0; kk < 16; ++kk) {
            ulonglong2 a01 = *(const ulonglong2*)&As[kk][ty << 3];
            ulonglong2 a23 = *(const ulonglong2*)&As[kk][(ty << 3) + 4];
            float4 b0 = *(const float4*)&Bs[kk][tx << 2];
            float4 b1 = *(const float4*)&Bs[kk][64 + (tx << 2)];
            u64 ar[4] = {a01.x, a01.y, a23.x, a23.y};
            u64 bd[8];
            bd[0] = pack2_(b0.x); bd[1] = pack2_(b0.y);
            bd[2] = pack2_(b0.z); bd[3] = pack2_(b0.w);
            bd[4] = pack2_(b1.x); bd[5] = pack2_(b1.y);
            bd[6] = pack2_(b1.z); bd[7] = pack2_(b1.w);
#pragma unroll
            for (int rp = 0; rp < 4; ++rp)
#pragma unroll
                for (int c = 0; c < 8; ++c) fma2_(acc[rp][c], ar[rp], bd[c]);
        }
        __syncthreads();
    }

    const bool partial = (gridDim.z > 1);
    float* obase = partial ? part + (size_t)z * M * Nn : Cm;
#pragma unroll
    for (int rp = 0; rp < 4; ++rp) {
        float lo[8], hi[8];
#pragma unroll
        for (int c = 0; c < 8; ++c) unpack2_(acc[rp][c], lo[c], hi[c]);
        int row0 = bm + (ty << 3) + rp * 2;
#pragma unroll
        for (int h = 0; h < 2; ++h) {
            int row = row0 + h;
            float* vv = h ? hi : lo;
            int colA = bn + (tx << 2);
            int colB = bn + 64 + (tx << 2);
            float4 oA, oB;
            if (!partial) {
                oA.x = epi_apply<EPI>(vv[0], row, colA + 0, Nn, e1, e2);
                oA.y = epi_apply<EPI>(vv[1], row, colA + 1, Nn, e1, e2);
                oA.z = epi_apply<EPI>(vv[2], row, colA + 2, Nn, e1, e2);
                oA.w = epi_apply<EPI>(vv[3], row, colA + 3, Nn, e1, e2);
                oB.x = epi_apply<EPI>(vv[4], row, colB + 0, Nn, e1, e2);
                oB.y = epi_apply<EPI>(vv[5], row, colB + 1, Nn, e1, e2);
                oB.z = epi_apply<EPI>(vv[6], row, colB + 2, Nn, e1, e2);
                oB.w = epi_apply<EPI>(vv[7], row, colB + 3, Nn, e1, e2);
            } else {
                oA = make_float4(vv[0], vv[1], vv[2], vv[3]);
                oB = make_float4(vv[4], vv[5], vv[6], vv[7]);
            }
            *(float4*)&obase[(size_t)row * Nn + colA] = oA;
            *(float4*)&obase[(size_t)row * Nn + colB] = oB;
        }
    }
}

__global__ void kreduce(const float* __restrict__ part, int S, size_t MN,
                        float* __restrict__ out)
{
    size_t i4 = ((size_t)blockIdx.x * 256 + threadIdx.x) * 4;
    if (i4 >= MN) return;
    float4 s = *(const float4*)&part[i4];
    for (int z = 1; z < S; ++z) {
        float4 v = *(const float4*)&part[(size_t)z * MN + i4];
        s.x += v.x; s.y += v.y; s.z += v.z; s.w += v.w;
    }
    *(float4*)&out[i4] = s;
}

// ------------------------- reductions / elementwise -------------------------
__global__ void colsum_part(const float* __restrict__ m, const float* __restrict__ w,
                            int rows, int cols, float* __restrict__ part)
{
    int c = blockIdx.x * 256 + threadIdx.x;
    int chunk = rows / gridDim.y;
    int r0 = blockIdx.y * chunk;
    float acc = 0.f;
    for (int r = r0; r < r0 + chunk; ++r)
        acc += m[(size_t)r * cols + c] * (w ? w[r] : 1.f);
    part[(size_t)blockIdx.y * cols + c] = acc;
}
__global__ void colsum_reduce(const float* __restrict__ part, int nb, int cols,
                              float* __restrict__ out)
{
    int c = blockIdx.x * 256 + threadIdx.x;
    float a = 0.f;
    for (int b = 0; b < nb; ++b) a += part[(size_t)b * cols + c];
    out[c] = a;
}

__global__ void s2c_kernel(const float* __restrict__ cm, const float* __restrict__ mv,
                           const float* __restrict__ den, float* __restrict__ s2c)
{
    int e = blockIdx.x * 256 + threadIdx.x;
    if (e >= N_ * C_) return;
    int i = e >> 9, c = e & (C_ - 1);
    float cv = cm[e];
    s2c[e] = cv * mv[i] / (den[c] * cv + 1.f);
}

__global__ void rownorm(const float* __restrict__ x, int cols,
                        float* __restrict__ nrm, float* __restrict__ vflag,
                        float* __restrict__ dg)
{
    int row = blockIdx.x * 8 + (threadIdx.x >> 5);
    int lane = threadIdx.x & 31;
    const float* p = x + (size_t)row * cols;
    float s = 0.f, q = 0.f;
    for (int c = lane; c < cols; c += 32) { float v = p[c]; s += v; q += v * v; }
#pragma unroll
    for (int o = 16; o; o >>= 1) {
        s += __shfl_xor_sync(0xffffffffu, s, o);
        q += __shfl_xor_sync(0xffffffffu, q, o);
    }
    if (lane == 0) {
        if (nrm) nrm[row] = sqrtf(q);
        if (vflag) vflag[row] = (s != 0.f) ? 1.f : 0.f;
        if (dg) { float d = sqrtf(q) * sqrtf(q); dg[row] = q / fmaxf(d, 1e-12f); }
    }
}

__global__ void row_softmax(float* __restrict__ m, int width,
                            const float* __restrict__ rs, const float* __restrict__ cs,
                            const float* __restrict__ vm)
{
    extern __shared__ float sv[];
    __shared__ float red[8];
    __shared__ float smx, ssum;
    const int tid = threadIdx.x, lane = tid & 31, wid = tid >> 5;
    const size_t base = (size_t)blockIdx.x * width;
    const float rsv = rs ? rs[blockIdx.x] : 0.f;
    float lmax = -3.0e38f;
    for (int j = tid; j < width; j += 256) {
        float v = m[base + j];
        if (rs) v = v / fmaxf(rsv * cs[j], 1e-12f);
        if (vm && vm[j] == 0.f) v = -3.0e38f;
        sv[j] = v;
        lmax = fmaxf(lmax, v);
    }
#pragma unroll
    for (int o = 16; o; o >>= 1) lmax = fmaxf(lmax, __shfl_xor_sync(0xffffffffu, lmax, o));
    if (lane == 0) red[wid] = lmax;
    __syncthreads();
    if (tid == 0) {
        float v = red[0];
        for (int w = 1; w < 8; ++w) v = fmaxf(v, red[w]);
        smx = v;
    }
    __syncthreads();
    const float mx = smx;
    float lsum = 0.f;
    for (int j = tid; j < width; j += 256) {
        float e = __expf(sv[j] - mx);
        sv[j] = e;
        lsum += e;
    }
#pragma unroll
    for (int o = 16; o; o >>= 1) lsum += __shfl_xor_sync(0xffffffffu, lsum, o);
    if (lane == 0) red[wid] = lsum;
    __syncthreads();
    if (tid == 0) {
        float v = 0.f;
        for (int w = 0; w < 8; ++w) v += red[w];
        ssum = v;
    }
    __syncthreads();
    const float inv = 1.f / ssum;
    for (int j = tid; j < width; j += 256) {
        float o = sv[j] * inv;
        if (vm) o = (vm[j] != 0.f) ? o : 0.f;
        m[base + j] = o;
    }
}

__global__ void topk_mask(float* __restrict__ m)
{
    __shared__ float vals[N_];
    __shared__ unsigned char flag[N_];
    __shared__ float rv[8];
    __shared__ int ri[8];
    const int tid = threadIdx.x, lane = tid & 31, wid = tid >> 5;
    const size_t base = (size_t)blockIdx.x * N_;
    for (int j = tid; j < N_; j += 256) { vals[j] = m[base + j]; flag[j] = 0; }
    __syncthreads();
    for (int s = 0; s < 10; ++s) {
        float bv = -3.0e38f; int bi = 0;
        for (int j = tid; j < N_; j += 256) {
            float v = vals[j];
            if (v > bv) { bv = v; bi = j; }
        }
#pragma unroll
        for (int o = 16; o; o >>= 1) {
            float ov = __shfl_down_sync(0xffffffffu, bv, o);
            int oi = __shfl_down_sync(0xffffffffu, bi, o);
            if (ov > bv || (ov == bv && oi < bi)) { bv = ov; bi = oi; }
        }
        if (lane == 0) { rv[wid] = bv; ri[wid] = bi; }
        __syncthreads();
        if (tid == 0) {
            float B = rv[0]; int I = ri[0];
            for (int w = 1; w < 8; ++w)
                if (rv[w] > B || (rv[w] == B && ri[w] < I)) { B = rv[w]; I = ri[w]; }
            flag[I] = 1;
            vals[I] = -3.0e38f;
        }
        __syncthreads();
    }
    for (int j = tid; j < N_; j += 256)
        if (!flag[j]) m[base + j] = 0.f;
}

__global__ void adddiag(float* __restrict__ big, const float* __restrict__ colsum,
                        const float* __restrict__ dg)
{
    int j = blockIdx.x * 256 + threadIdx.x;
    if (j < N_ && colsum[j] != 0.f)
        big[(size_t)j * N_ + j] += dg[j];
}

__global__ void final_head(const float* __restrict__ a, const float* __restrict__ b,
                           const float* __restrict__ c, const float* __restrict__ w,
                           const float* __restrict__ bo, float* __restrict__ out)
{
    int row = blockIdx.x * 8 + (threadIdx.x >> 5);
    int lane = threadIdx.x & 31;
    size_t base = (size_t)row * H_;
    float acc = 0.f;
    for (int h = lane; h < H_; h += 32)
        acc += (a[base + h] + b[base + h] + c[base + h]) * w[h];
#pragma unroll
    for (int o = 16; o; o >>= 1) acc += __shfl_xor_sync(0xffffffffu, acc, o);
    if (lane == 0) out[row] = acc + bo[0];
}

// ------------------------- host side -------------------------
static float* g_kpart_ptr;

static void gemm(int TR, int EPI, const float* A, const float* B, float* Cm,
                 int M, int Nn, int K, int S, const float* e1, const float* e2)
{
    dim3 g(Nn / 128, M / 128, S), blk(256);
    int Ks = K / S;
    if (S > 1) {
        if (TR == 0) sgemm128<0, 0><<<g, blk>>>(A, B, Cm, M, Nn, K, Ks, e1, e2, g_kpart_ptr);
        else if (TR == 1) sgemm128<1, 0><<<g, blk>>>(A, B, Cm, M, Nn, K, Ks, e1, e2, g_kpart_ptr);
        else sgemm128<2, 0><<<g, blk>>>(A, B, Cm, M, Nn, K, Ks, e1, e2, g_kpart_ptr);
        size_t MN = (size_t)M * Nn;
        kreduce<<<(int)((MN / 4 + 255) / 256), 256>>>(g_kpart_ptr, S, MN, Cm);
        return;
    }
    if (TR == 0) sgemm128<0, 0><<<g, blk>>>(A, B, Cm, M, Nn, K, Ks, e1, e2, nullptr);
    else if (TR == 2) sgemm128<2, 0><<<g, blk>>>(A, B, Cm, M, Nn, K, Ks, e1, e2, nullptr);
    else if (EPI == 0) sgemm128<1, 0><<<g, blk>>>(A, B, Cm, M, Nn, K, Ks, e1, e2, nullptr);
    else if (EPI == 1) sgemm128<1, 1><<<g, blk>>>(A, B, Cm, M, Nn, K, Ks, e1, e2, nullptr);
    else if (EPI == 2) sgemm128<1, 2><<<g, blk>>>(A, B, Cm, M, Nn, K, Ks, e1, e2, nullptr);
    else sgemm128<1, 3><<<g, blk>>>(A, B, Cm, M, Nn, K, Ks, e1, e2, nullptr);
}

static void mm_go(int EPI, const float* A, const float* B, float* Cm,
                  int M, int Nn, const float* e1, const float* e2)
{
    dim3 g(Nn / 128, M / 128);
    if (EPI == 0) mmagemm<0><<<g, 256, MM_SMEM>>>(A, B, Cm, M, Nn, e1, e2);
    else if (EPI == 1) mmagemm<1><<<g, 256, MM_SMEM>>>(A, B, Cm, M, Nn, e1, e2);
    else mmagemm<4><<<g, 256, MM_SMEM>>>(A, B, Cm, M, Nn, e1, e2);
}

template <typename Tp>
static float* symaddr(Tp& sym)
{
    void* p = nullptr;
    cudaGetSymbolAddress(&p, sym);
    return (float*)p;
}

extern "C" void kernel_launch(void* const* d_in, const int* in_sizes, int n_in,
                              void* d_out, int out_size)
{
    const float* x = (const float*)d_in[0];
    const float* cm = (const float*)d_in[1];
    const float* mv = (const float*)d_in[2];
    const float* wih0 = (const float*)d_in[3];
    const float* whh0 = (const float*)d_in[4];
    const float* bih0 = (const float*)d_in[5];
    const float* bhh0 = (const float*)d_in[6];
    const float* wih1 = (const float*)d_in[7];
    const float* whh1 = (const float*)d_in[8];
    const float* bih1 = (const float*)d_in[9];
    const float* bhh1 = (const float*)d_in[10];
    const float* w_ps = (const float*)d_in[11];
    const float* b_ps = (const float*)d_in[12];
    const float* w_hs = (const float*)d_in[13];
    const float* b_hs = (const float*)d_in[14];
    const float* w_ps_fore = (const float*)d_in[15];
    const float* b_ps_fore = (const float*)d_in[16];
    const float* w_hs_fore = (const float*)d_in[17];
    const float* b_hs_fore = (const float*)d_in[18];
    const float* w_ps_back = (const float*)d_in[19];
    const float* b_ps_back = (const float*)d_in[20];
    const float* w_hs_back = (const float*)d_in[21];
    const float* b_hs_back = (const float*)d_in[22];
    const float* w_indi = (const float*)d_in[23];
    const float* b_indi = (const float*)d_in[24];
    const float* w_out = (const float*)d_in[25];
    const float* b_out = (const float*)d_in[26];
    float* out = (float*)d_out;

    float* gx = symaddr(g_gx);
    float* out0 = symaddr(g_out0);
    float* xh = symaddr(g_xh);
    float* den = symaddr(g_den);
    float* s2c = symaddr(g_s2c);
    float* hidC = symaddr(g_hidC);
    float* v1 = symaddr(g_v1);
    float* logits = symaddr(g_logits);
    float* hid2 = symaddr(g_hid2);
    float* nx = symaddr(g_nx);
    float* ny = symaddr(g_ny);
    float* c2s = symaddr(g_c2s);
    float* tmp = symaddr(g_tmp);
    float* ps = symaddr(g_ps);
    float* hsh = symaddr(g_hsh);
    float* outps = symaddr(g_outps);
    float* nh = symaddr(g_nh);
    float* dg = symaddr(g_diag);
    float* big = symaddr(g_big);
    float* part = symaddr(g_part);
    float* colsum = symaddr(g_colsum);
    float* hidH = symaddr(g_hidH);
    float* v2 = symaddr(g_v2);
    float* nhh = symaddr(g_nhh);
    float* hsi = symaddr(g_hsi);
    float* indi = symaddr(g_indi);
    float* ouths = symaddr(g_ouths);
    float* outindi = symaddr(g_outindi);
    g_kpart_ptr = symaddr(g_kpart);

    const int GRU_SMEM = (128 * G3 + 128 * 33 + G3) * 4;
    cudaFuncSetAttribute(gru_layer, cudaFuncAttributeMaxDynamicSharedMemorySize, GRU_SMEM);
    cudaFuncSetAttribute(mmagemm<0>, cudaFuncAttributeMaxDynamicSharedMemorySize, MM_SMEM);
    cudaFuncSetAttribute(mmagemm<1>, cudaFuncAttributeMaxDynamicSharedMemorySize, MM_SMEM);
    cudaFuncSetAttribute(mmagemm<4>, cudaFuncAttributeMaxDynamicSharedMemorySize, MM_SMEM);

    // ---- GRU ----
    gx0_kernel<<<dim3(T_, N_ / 32), G3>>>(x, wih0, bih0, gx);
    gru_layer<<<N_ / 32, 512, GRU_SMEM>>>(gx, whh0, bhh0, out0, 1);
    mm_go(1, out0, wih1, gx, T_ * N_, G3, bih1, nullptr);              // gx1 (HMMA)
    gru_layer<<<N_ / 32, 512, GRU_SMEM>>>(gx, whh1, bhh1, xh, 0);

    // ---- predefined-concept branch ----
    colsum_part<<<dim3(C_ / 256, 32), 256>>>(cm, mv, N_, C_, part);
    colsum_reduce<<<C_ / 256, 256>>>(part, 32, C_, den);
    s2c_kernel<<<(N_ * C_) / 256, 256>>>(cm, mv, den, s2c);
    gemm(2, 0, s2c, xh, hidC, C_, H_, N_, 16, nullptr, nullptr);       // hidden = s2c^T @ xh
    rownorm<<<C_ / 8, 256>>>(hidC, H_, nullptr, v1, nullptr);
    mm_go(0, hidC, xh, logits, C_, N_, nullptr, nullptr);              // logits^T (HMMA)
    row_softmax<<<C_, 256, N_ * 4>>>(logits, N_, nullptr, nullptr, nullptr);
    gemm(0, 0, logits, xh, hid2, C_, H_, N_, 16, nullptr, nullptr);    // hidden2
    rownorm<<<N_ / 8, 256>>>(xh, H_, nx, nullptr, nullptr);
    rownorm<<<C_ / 8, 256>>>(hid2, H_, ny, nullptr, nullptr);
    mm_go(0, xh, hid2, c2s, N_, C_, nullptr, nullptr);                 // cos numerator (HMMA)
    row_softmax<<<N_, 256, C_ * 4>>>(c2s, C_, nx, ny, v1);
    gemm(0, 0, c2s, hid2, tmp, N_, H_, C_, 4, nullptr, nullptr);       // p_shared0
    gemm(1, 1, tmp, w_ps, ps, N_, H_, H_, 1, b_ps, nullptr);           // p_shared
    gemm(1, 3, ps, w_ps_back, hsh, N_, H_, H_, 1, b_ps_back, xh);      // h_shared
    gemm(1, 2, ps, w_ps_fore, outps, N_, H_, H_, 1, b_ps_fore, nullptr);

    // ---- hidden-concept branch ----
    rownorm<<<N_ / 8, 256>>>(hsh, H_, nh, nullptr, dg);
    mm_go(4, hsh, hsh, big, N_, N_, nh, nh);                           // hs2c (HMMA, fused)
    topk_mask<<<N_, 256>>>(big);
    colsum_part<<<dim3(N_ / 256, 32), 256>>>(big, nullptr, N_, N_, part);
    colsum_reduce<<<N_ / 256, 256>>>(part, 32, N_, colsum);
    adddiag<<<N_ / 256, 256>>>(big, colsum, dg);
    gemm(2, 0, big, hsh, hidH, N_, H_, N_, 16, nullptr, nullptr);      // hidden_h
    rownorm<<<N_ / 8, 256>>>(hidH, H_, nhh, v2, nullptr);
    mm_go(0, hsh, hidH, big, N_, N_, nullptr, nullptr);                // hc2s numerator (HMMA)
    row_softmax<<<N_, 256, N_ * 4>>>(big, N_, nh, nhh, v2);
    gemm(0, 0, big, hidH, tmp, N_, H_, N_, 16, nullptr, nullptr);      // h_si0
    gemm(1, 1, tmp, w_hs, hsi, N_, H_, H_, 1, b_hs, nullptr);          // h_si
    gemm(1, 3, hsi, w_hs_back, indi, N_, H_, H_, 1, b_hs_back, hsh);   // indi
    gemm(1, 2, hsi, w_hs_fore, ouths, N_, H_, H_, 1, b_hs_fore, nullptr);
    gemm(1, 2, indi, w_indi, outindi, N_, H_, H_, 1, b_indi, nullptr);

    // ---- head ----
    final_head<<<N_ / 8, 256>>>(outps, ouths, outindi, w_out, b_out, out);
}